// round 1
// baseline (speedup 1.0000x reference)
#include <cuda_runtime.h>
#include <cstdint>
#include <cstddef>

// ---------------------------------------------------------------------------
// Problem: B=4, L=2048, D=1024, H=16, Hd=64
//   qkv = x @ W_attn + b_attn            [8192 x 3072]
//   attn (causal, 16 heads, softmax)      -> o [8192 x 1024]
//   out = o @ W_proj + b_proj             [8192 x 1024]
// ---------------------------------------------------------------------------

#define Bq 4
#define Lq 2048
#define Dq 1024
#define Hq 16
#define HDq 64

// Scratch (device globals; allocation is forbidden)
__device__ float g_q[Bq * Hq * Lq * HDq];   // [B,H,L,Hd]
__device__ float g_k[Bq * Hq * Lq * HDq];
__device__ float g_v[Bq * Hq * Lq * HDq];
__device__ float g_o[Bq * Lq * Hq * HDq];   // [B,L,H,Hd] == [8192,1024] row-major

typedef unsigned long long u64t;

__device__ __forceinline__ u64t pack2(float lo, float hi) {
    u64t r;
    asm("mov.b64 %0, {%1, %2};" : "=l"(r) : "f"(lo), "f"(hi));
    return r;
}
__device__ __forceinline__ void fma2(u64t& d, u64t a, u64t b) {
    asm("fma.rn.f32x2 %0, %1, %2, %3;" : "=l"(d) : "l"(a), "l"(b), "l"(d));
}
__device__ __forceinline__ float2 unpack2(u64t v) {
    float2 r;
    asm("mov.b64 {%0, %1}, %2;" : "=f"(r.x), "=f"(r.y) : "l"(v));
    return r;
}

// ---------------------------------------------------------------------------
// SGEMM: C[M,N] = A[M,K] @ B[K,N] + bias[N]
// 128x128x16 tile, 256 threads, 8x8 per thread, inner loop on fma.rn.f32x2.
// mode 0: store C row-major.
// mode 1: scatter qkv columns into g_q/g_k/g_v laid out [B,H,L,Hd].
// ---------------------------------------------------------------------------
__global__ __launch_bounds__(256, 2)
void sgemm_kernel(const float* __restrict__ A, const float* __restrict__ Bm,
                  const float* __restrict__ bias, float* __restrict__ C,
                  int M, int N, int K, int mode,
                  float* __restrict__ qout, float* __restrict__ kout,
                  float* __restrict__ vout) {
    __shared__ float As[16][128];   // k-major (transposed A tile)
    __shared__ float Bs[16][128];

    const int tid = threadIdx.x;
    const int bm = blockIdx.y * 128;
    const int bn = blockIdx.x * 128;

    const int arow  = tid >> 2;          // 0..63 (plus +64)
    const int acol4 = (tid & 3) * 4;     // 0,4,8,12
    const int brow  = tid >> 5;          // 0..7 (plus +8)
    const int bcol4 = (tid & 31) * 4;    // 0..124

    const int tx = tid & 15;
    const int ty = tid >> 4;

    u64t acc2[8][4];
    #pragma unroll
    for (int i = 0; i < 8; i++)
        #pragma unroll
        for (int j = 0; j < 4; j++) acc2[i][j] = 0ULL;

    for (int k0 = 0; k0 < K; k0 += 16) {
        // Load A tile (transposed into As[k][m])
        #pragma unroll
        for (int r = 0; r < 2; r++) {
            int row = arow + r * 64;
            float4 a = *(const float4*)(A + (size_t)(bm + row) * K + k0 + acol4);
            As[acol4 + 0][row] = a.x;
            As[acol4 + 1][row] = a.y;
            As[acol4 + 2][row] = a.z;
            As[acol4 + 3][row] = a.w;
        }
        // Load B tile
        #pragma unroll
        for (int r = 0; r < 2; r++) {
            int row = brow + r * 8;
            *(float4*)&Bs[row][bcol4] =
                *(const float4*)(Bm + (size_t)(k0 + row) * N + bn + bcol4);
        }
        __syncthreads();

        #pragma unroll
        for (int kk = 0; kk < 16; kk++) {
            float a[8];
            *(float4*)&a[0] = *(const float4*)&As[kk][ty * 4];
            *(float4*)&a[4] = *(const float4*)&As[kk][64 + ty * 4];
            const float* bp = &Bs[kk][tx * 4];
            u64t b2[4];
            b2[0] = *(const u64t*)(bp);
            b2[1] = *(const u64t*)(bp + 2);
            b2[2] = *(const u64t*)(bp + 64);
            b2[3] = *(const u64t*)(bp + 66);
            #pragma unroll
            for (int i = 0; i < 8; i++) {
                u64t a2 = pack2(a[i], a[i]);
                fma2(acc2[i][0], a2, b2[0]);
                fma2(acc2[i][1], a2, b2[1]);
                fma2(acc2[i][2], a2, b2[2]);
                fma2(acc2[i][3], a2, b2[3]);
            }
        }
        __syncthreads();
    }

    // Epilogue
    #pragma unroll
    for (int i = 0; i < 8; i++) {
        int m = bm + ((i < 4) ? (ty * 4 + i) : (64 + ty * 4 + i - 4));
        #pragma unroll
        for (int j2 = 0; j2 < 4; j2++) {
            int n = bn + ((j2 < 2) ? (tx * 4 + j2 * 2) : (64 + tx * 4 + (j2 - 2) * 2));
            float2 val = unpack2(acc2[i][j2]);
            val.x += bias[n];
            val.y += bias[n + 1];
            if (mode == 0) {
                *(float2*)(C + (size_t)m * N + n) = val;
            } else {
                // n even, pair stays within one head (Hd=64 aligned) and one of q/k/v
                int which = n >> 10;
                int rem = n & 1023;
                int h = rem >> 6;
                int d = rem & 63;
                int b = m >> 11;
                int l = m & 2047;
                float* dst = (which == 0) ? qout : (which == 1) ? kout : vout;
                size_t di = (((size_t)(b * Hq + h)) * Lq + l) * HDq + d;
                *(float2*)(dst + di) = val;
            }
        }
    }
}

// ---------------------------------------------------------------------------
// Flash attention (causal). One block per (b*H+h, q-tile of 128 rows).
// Bc = 64 key columns per inner step. 256 threads.
// Per-thread patches: S -> 8(i) x 4(j); O -> 8(i) x 4(d).
// ---------------------------------------------------------------------------
#define ATTN_PAD 68   // row stride in floats (16B aligned, decorrelates banks)
#define ATTN_SMEM_FLOATS (128 * ATTN_PAD /*Q*/ + 128 * ATTN_PAD /*S*/ + \
                          64 * ATTN_PAD /*K*/ + 64 * ATTN_PAD /*V*/ + 3 * 128)
#define ATTN_SMEM_BYTES (ATTN_SMEM_FLOATS * 4)

__global__ __launch_bounds__(256, 2)
void attn_kernel(const float* __restrict__ q, const float* __restrict__ k,
                 const float* __restrict__ v, float* __restrict__ o) {
    extern __shared__ float sm[];
    float* Qs = sm;                    // [128][ATTN_PAD]
    float* Ss = Qs + 128 * ATTN_PAD;   // [128][ATTN_PAD]
    float* Ks = Ss + 128 * ATTN_PAD;   // [64][ATTN_PAD]
    float* Vs = Ks + 64 * ATTN_PAD;    // [64][ATTN_PAD]
    float* mrow = Vs + 64 * ATTN_PAD;  // [128]
    float* lrow = mrow + 128;          // [128]
    float* arow = lrow + 128;          // [128]

    const int bh = blockIdx.y;                       // b*16 + h
    const int qt = (int)gridDim.x - 1 - blockIdx.x;  // heavy tiles first
    const int tid = threadIdx.x;
    const int tx = tid & 15;   // j / d patch base: tx*4
    const int ty = tid >> 4;   // i patch base: ty*8
    const size_t base = (size_t)bh * Lq * HDq;
    const int q0 = qt * 128;

    // Load + pre-scale Q tile (scale = 1/sqrt(64) = 0.125)
    for (int idx = tid; idx < 128 * 16; idx += 256) {
        int row = idx >> 4;
        int c4 = (idx & 15) << 2;
        float4 t = *(const float4*)(q + base + (size_t)(q0 + row) * HDq + c4);
        float* dst = &Qs[row * ATTN_PAD + c4];
        dst[0] = t.x * 0.125f;
        dst[1] = t.y * 0.125f;
        dst[2] = t.z * 0.125f;
        dst[3] = t.w * 0.125f;
    }
    if (tid < 128) {
        mrow[tid] = -1e30f;
        lrow[tid] = 0.0f;
    }

    float accO[8][4];
    #pragma unroll
    for (int i = 0; i < 8; i++)
        #pragma unroll
        for (int d = 0; d < 4; d++) accO[i][d] = 0.0f;

    const int nkt = 2 * qt + 2;
    for (int kt = 0; kt < nkt; kt++) {
        const int k0 = kt * 64;
        __syncthreads();   // previous iteration done with Ks/Vs/Ss; Qs ready (kt==0)

        // Load K,V tiles (64 x 64)
        for (int idx = tid; idx < 64 * 16; idx += 256) {
            int row = idx >> 4;
            int c4 = (idx & 15) << 2;
            *(float4*)&Ks[row * ATTN_PAD + c4] =
                *(const float4*)(k + base + (size_t)(k0 + row) * HDq + c4);
            *(float4*)&Vs[row * ATTN_PAD + c4] =
                *(const float4*)(v + base + (size_t)(k0 + row) * HDq + c4);
        }
        __syncthreads();

        // S = Qs @ Ks^T  (patch 8x4 per thread)
        float sacc[8][4];
        #pragma unroll
        for (int i = 0; i < 8; i++)
            #pragma unroll
            for (int j = 0; j < 4; j++) sacc[i][j] = 0.0f;

        #pragma unroll 2
        for (int d = 0; d < 64; d += 4) {
            float br[4][4];
            #pragma unroll
            for (int j = 0; j < 4; j++)
                *(float4*)br[j] = *(const float4*)&Ks[(tx * 4 + j) * ATTN_PAD + d];
            #pragma unroll
            for (int i = 0; i < 8; i++) {
                float ar[4];
                *(float4*)ar = *(const float4*)&Qs[(ty * 8 + i) * ATTN_PAD + d];
                #pragma unroll
                for (int j = 0; j < 4; j++)
                    #pragma unroll
                    for (int dd = 0; dd < 4; dd++)
                        sacc[i][j] += ar[dd] * br[j][dd];
            }
        }

        // mask + write S to smem
        const bool masked_tile = (kt >= 2 * qt);
        #pragma unroll
        for (int i = 0; i < 8; i++) {
            int ig = q0 + ty * 8 + i;
            #pragma unroll
            for (int j = 0; j < 4; j++) {
                int jg = k0 + tx * 4 + j;
                float sv = sacc[i][j];
                if (masked_tile && jg > ig) sv = -1e30f;
                Ss[(ty * 8 + i) * ATTN_PAD + tx * 4 + j] = sv;
            }
        }
        __syncthreads();

        // online softmax, one thread per row
        if (tid < 128) {
            float mold = mrow[tid];
            float mx = mold;
            float* srow = &Ss[tid * ATTN_PAD];
            #pragma unroll 8
            for (int j = 0; j < 64; j++) mx = fmaxf(mx, srow[j]);
            float al = __expf(mold - mx);
            float sum = 0.0f;
            #pragma unroll 8
            for (int j = 0; j < 64; j++) {
                float p = __expf(srow[j] - mx);
                srow[j] = p;
                sum += p;
            }
            lrow[tid] = lrow[tid] * al + sum;
            mrow[tid] = mx;
            arow[tid] = al;
        }
        __syncthreads();

        // rescale accumulators
        #pragma unroll
        for (int i = 0; i < 8; i++) {
            float al = arow[ty * 8 + i];
            #pragma unroll
            for (int dd = 0; dd < 4; dd++) accO[i][dd] *= al;
        }

        // O += P @ V   (patch 8x4 per thread)
        #pragma unroll 2
        for (int j = 0; j < 64; j += 4) {
            float vr[4][4];
            #pragma unroll
            for (int jj = 0; jj < 4; jj++)
                *(float4*)vr[jj] = *(const float4*)&Vs[(j + jj) * ATTN_PAD + tx * 4];
            #pragma unroll
            for (int i = 0; i < 8; i++) {
                float pr[4];
                *(float4*)pr = *(const float4*)&Ss[(ty * 8 + i) * ATTN_PAD + j];
                #pragma unroll
                for (int jj = 0; jj < 4; jj++)
                    #pragma unroll
                    for (int dd = 0; dd < 4; dd++)
                        accO[i][dd] += pr[jj] * vr[jj][dd];
            }
        }
    }

    // Final normalize + write o [B,L,H,Hd]
    const int b = bh >> 4;
    const int h = bh & 15;
    #pragma unroll
    for (int i = 0; i < 8; i++) {
        int row = q0 + ty * 8 + i;
        float linv = 1.0f / lrow[ty * 8 + i];
        float4 t;
        t.x = accO[i][0] * linv;
        t.y = accO[i][1] * linv;
        t.z = accO[i][2] * linv;
        t.w = accO[i][3] * linv;
        size_t dst = (((size_t)b * Lq + row) * Hq + h) * HDq + tx * 4;
        *(float4*)(o + dst) = t;
    }
}

// ---------------------------------------------------------------------------
// Launch
// ---------------------------------------------------------------------------
extern "C" void kernel_launch(void* const* d_in, const int* in_sizes, int n_in,
                              void* d_out, int out_size) {
    const float* x  = (const float*)d_in[0];
    const float* Wa = (const float*)d_in[1];
    const float* ba = (const float*)d_in[2];
    const float* Wp = (const float*)d_in[3];
    const float* bp = (const float*)d_in[4];
    float* out = (float*)d_out;

    float *gq, *gk, *gv, *go;
    cudaGetSymbolAddress((void**)&gq, g_q);
    cudaGetSymbolAddress((void**)&gk, g_k);
    cudaGetSymbolAddress((void**)&gv, g_v);
    cudaGetSymbolAddress((void**)&go, g_o);

    // 1) QKV projection: [8192,1024] @ [1024,3072], scatter to q/k/v [B,H,L,Hd]
    sgemm_kernel<<<dim3(3072 / 128, 8192 / 128), 256>>>(
        x, Wa, ba, nullptr, 8192, 3072, 1024, 1, gq, gk, gv);

    // 2) causal flash attention
    cudaFuncSetAttribute(attn_kernel, cudaFuncAttributeMaxDynamicSharedMemorySize,
                         ATTN_SMEM_BYTES);
    attn_kernel<<<dim3(Lq / 128, Bq * Hq), 256, ATTN_SMEM_BYTES>>>(gq, gk, gv, go);

    // 3) output projection: [8192,1024] @ [1024,1024] + bias -> out
    sgemm_kernel<<<dim3(1024 / 128, 8192 / 128), 256>>>(
        go, Wp, bp, out, 8192, 1024, 1024, 0, nullptr, nullptr, nullptr);
}

// round 8
// speedup vs baseline: 1.3701x; 1.3701x over previous
#include <cuda_runtime.h>
#include <cuda_bf16.h>
#include <cstdint>
#include <cstddef>

// ---------------------------------------------------------------------------
// Problem: B=4, L=2048, D=1024, H=16, Hd=64
//   qkv = x @ W_attn + b_attn            [8192 x 3072]
//   attn (causal, 16 heads, softmax)      -> o [8192 x 1024]
//   out = o @ W_proj + b_proj             [8192 x 1024]
// Round 7 resubmit of round 4 (infra failure, never measured):
// dense GEMMs on mma.sync bf16 (hi/lo split, 3-pass, fp32 accum).
// tcgen05 is unusable: harness PTX targets sm_103 (no 'a' feature set).
// ---------------------------------------------------------------------------

#define Bq 4
#define Lq 2048
#define Dq 1024
#define Hq 16
#define HDq 64

// fp32 scratch
__device__ float g_q[Bq * Hq * Lq * HDq];   // [B,H,L,Hd]
__device__ float g_k[Bq * Hq * Lq * HDq];
__device__ float g_v[Bq * Hq * Lq * HDq];
__device__ float g_o[Bq * Lq * Hq * HDq];   // [B,L,H,Hd] == [8192,1024]

// bf16 split scratch
__device__ __nv_bfloat16 g_ahi[8192 * 1024];
__device__ __nv_bfloat16 g_alo[8192 * 1024];
__device__ __nv_bfloat16 g_wahi[3072 * 1024];  // W_attn^T split
__device__ __nv_bfloat16 g_walo[3072 * 1024];
__device__ __nv_bfloat16 g_wphi[1024 * 1024];  // W_proj^T split
__device__ __nv_bfloat16 g_wplo[1024 * 1024];

__device__ __forceinline__ uint32_t smem_to_u32(const void* p) {
    uint32_t a;
    asm("{ .reg .u64 t; cvta.to.shared.u64 t, %1; cvt.u32.u64 %0, t; }"
        : "=r"(a) : "l"(p));
    return a;
}

#define LDMATRIX_X4(r0, r1, r2, r3, addr) \
    asm volatile("ldmatrix.sync.aligned.m8n8.x4.shared.b16 {%0,%1,%2,%3}, [%4];" \
                 : "=r"(r0), "=r"(r1), "=r"(r2), "=r"(r3) : "r"(addr))

#define MMA_BF16(c, a, b) \
    asm volatile( \
        "mma.sync.aligned.m16n8k16.row.col.f32.bf16.bf16.f32 " \
        "{%0,%1,%2,%3}, {%4,%5,%6,%7}, {%8,%9}, {%0,%1,%2,%3};" \
        : "+f"((c)[0]), "+f"((c)[1]), "+f"((c)[2]), "+f"((c)[3]) \
        : "r"((a)[0]), "r"((a)[1]), "r"((a)[2]), "r"((a)[3]), \
          "r"((b)[0]), "r"((b)[1]))

#define CP_ASYNC16(dst, src) \
    asm volatile("cp.async.cg.shared.global [%0], [%1], 16;" \
                 :: "r"(dst), "l"(src))
#define CP_COMMIT() asm volatile("cp.async.commit_group;" ::: "memory")

// ---------------------------------------------------------------------------
// Split kernels: fp32 -> bf16 hi + bf16 lo
// ---------------------------------------------------------------------------
__global__ void split_kernel(const float* __restrict__ in,
                             __nv_bfloat16* __restrict__ hi,
                             __nv_bfloat16* __restrict__ lo, int n) {
    int i = (blockIdx.x * blockDim.x + threadIdx.x) * 4;
    if (i >= n) return;
    float4 v = *(const float4*)(in + i);
    __nv_bfloat16 h0 = __float2bfloat16(v.x);
    __nv_bfloat16 h1 = __float2bfloat16(v.y);
    __nv_bfloat16 h2 = __float2bfloat16(v.z);
    __nv_bfloat16 h3 = __float2bfloat16(v.w);
    __nv_bfloat16 l0 = __float2bfloat16(v.x - __bfloat162float(h0));
    __nv_bfloat16 l1 = __float2bfloat16(v.y - __bfloat162float(h1));
    __nv_bfloat16 l2 = __float2bfloat16(v.z - __bfloat162float(h2));
    __nv_bfloat16 l3 = __float2bfloat16(v.w - __bfloat162float(h3));
    *(__nv_bfloat162*)(hi + i)     = __nv_bfloat162(h0, h1);
    *(__nv_bfloat162*)(hi + i + 2) = __nv_bfloat162(h2, h3);
    *(__nv_bfloat162*)(lo + i)     = __nv_bfloat162(l0, l1);
    *(__nv_bfloat162*)(lo + i + 2) = __nv_bfloat162(l2, l3);
}

// W [1024, Ncols] -> Wt hi/lo [Ncols, 1024]  (transpose + split)
__global__ void wsplit_kernel(const float* __restrict__ W,
                              __nv_bfloat16* __restrict__ hi,
                              __nv_bfloat16* __restrict__ lo, int Ncols) {
    __shared__ float t[32][33];
    int n0 = blockIdx.x * 32, k0 = blockIdx.y * 32;
    int tx = threadIdx.x & 31, ty = threadIdx.x >> 5;  // 32 x 8
    #pragma unroll
    for (int r = 0; r < 32; r += 8)
        t[ty + r][tx] = W[(size_t)(k0 + ty + r) * Ncols + n0 + tx];
    __syncthreads();
    #pragma unroll
    for (int r = 0; r < 32; r += 8) {
        float v = t[tx][ty + r];  // W[k0+tx][n0+ty+r]
        __nv_bfloat16 h = __float2bfloat16(v);
        size_t di = (size_t)(n0 + ty + r) * 1024 + k0 + tx;
        hi[di] = h;
        lo[di] = __float2bfloat16(v - __bfloat162float(h));
    }
}

// ---------------------------------------------------------------------------
// mma.sync GEMM: C[M,N] = Asplit[M,1024] @ Bsplit[N,1024]^T + bias
// 128x128 CTA tile, 8 warps (2x4 -> 64x32 warp tile), Kc=32 chunks,
// 3-stage cp.async pipeline, hi/lo 3-pass accumulation.
// smem rows padded to 40 bf16 (80B = 5x16B) -> conflict-free ldmatrix.
// mode 0: row-major C store. mode 1: qkv scatter to [B,H,L,Hd].
// ---------------------------------------------------------------------------
#define KCH 32                         // k per chunk
#define NCHUNK 32                      // 1024 / 32
#define ROWP 40                        // padded row in bf16
#define TILEB (128 * ROWP * 2)         // 10240 bytes per tile
#define STAGEB (4 * TILEB)             // Ahi, Alo, Bhi, Blo
#define NSTAGE 3
#define GEMM_SMEM (NSTAGE * STAGEB)    // 122880

__global__ __launch_bounds__(256)
void mma_gemm(const __nv_bfloat16* __restrict__ Ahi,
              const __nv_bfloat16* __restrict__ Alo,
              const __nv_bfloat16* __restrict__ Bhi,
              const __nv_bfloat16* __restrict__ Blo,
              const float* __restrict__ bias, float* __restrict__ C, int N,
              int mode, float* __restrict__ qo, float* __restrict__ ko,
              float* __restrict__ vo) {
    extern __shared__ __align__(128) char smem[];
    const uint32_t smem_u32 = smem_to_u32(smem);
    const int tid = threadIdx.x;
    const int wid = tid >> 5;
    const int lane = tid & 31;
    const int wm = wid >> 2;           // 0..1  (m: 64 each)
    const int wn = wid & 3;            // 0..3  (n: 32 each)
    const int bn = blockIdx.x * 128;
    const int bm = blockIdx.y * 128;

    float acc[4][4][4];
    #pragma unroll
    for (int mt = 0; mt < 4; mt++)
        #pragma unroll
        for (int nt = 0; nt < 4; nt++)
            #pragma unroll
            for (int r = 0; r < 4; r++) acc[mt][nt][r] = 0.0f;

    // ---- stage loader: 4 tiles x 128 rows x 32 bf16 (2 cp.async / thread / tile)
    auto load_stage = [&](int kc, int stage) {
        const int k0 = kc * KCH;
        const uint32_t sb = smem_u32 + stage * STAGEB;
        #pragma unroll
        for (int t = 0; t < 4; t++) {
            const __nv_bfloat16* src =
                (t == 0) ? Ahi : (t == 1) ? Alo : (t == 2) ? Bhi : Blo;
            const int rbase = (t < 2) ? bm : bn;
            #pragma unroll
            for (int s = 0; s < 2; s++) {
                int idx = s * 256 + tid;       // 0..511
                int row = idx >> 2;            // 0..127
                int c4 = idx & 3;              // 16B chunk
                const void* g = src + (size_t)(rbase + row) * 1024 + k0 + c4 * 8;
                uint32_t d = sb + t * TILEB + row * 80 + c4 * 16;
                CP_ASYNC16(d, g);
            }
        }
        CP_COMMIT();
    };

    load_stage(0, 0);
    load_stage(1, 1);

    // fragment address components (constant over loop)
    const int amat = lane >> 3;
    const int rowin = lane & 7;
    const int am_base = wm * 64 + (amat & 1) * 8 + rowin;  // + mt*16
    const int ak_base = (amat >> 1) * 8;                    // + kb
    const int bn_base = wn * 32 + ((lane >> 3) >> 1) * 8 + rowin;  // + np*16
    const int bk_base = ((lane >> 3) & 1) * 8;                      // + kb

    for (int kc = 0; kc < NCHUNK; kc++) {
        if (kc < NCHUNK - 1)
            asm volatile("cp.async.wait_group 1;" ::: "memory");
        else
            asm volatile("cp.async.wait_group 0;" ::: "memory");
        __syncthreads();

        if (kc + 2 < NCHUNK) load_stage(kc + 2, (kc + 2) % NSTAGE);

        const uint32_t sb = smem_u32 + (kc % NSTAGE) * STAGEB;
        #pragma unroll
        for (int ks = 0; ks < 2; ks++) {
            const int kb = ks * 16;
            uint32_t ah[4][4], al[4][4], bh[4][2], bl[4][2];
            #pragma unroll
            for (int mt = 0; mt < 4; mt++) {
                uint32_t a = sb + (am_base + mt * 16) * 80 + (ak_base + kb) * 2;
                LDMATRIX_X4(ah[mt][0], ah[mt][1], ah[mt][2], ah[mt][3], a);
                LDMATRIX_X4(al[mt][0], al[mt][1], al[mt][2], al[mt][3], a + TILEB);
            }
            #pragma unroll
            for (int np = 0; np < 2; np++) {
                uint32_t b = sb + 2 * TILEB + (bn_base + np * 16) * 80 +
                             (bk_base + kb) * 2;
                LDMATRIX_X4(bh[np * 2][0], bh[np * 2][1],
                            bh[np * 2 + 1][0], bh[np * 2 + 1][1], b);
                LDMATRIX_X4(bl[np * 2][0], bl[np * 2][1],
                            bl[np * 2 + 1][0], bl[np * 2 + 1][1], b + TILEB);
            }
            #pragma unroll
            for (int mt = 0; mt < 4; mt++)
                #pragma unroll
                for (int nt = 0; nt < 4; nt++) {
                    MMA_BF16(acc[mt][nt], ah[mt], bh[nt]);
                    MMA_BF16(acc[mt][nt], ah[mt], bl[nt]);
                    MMA_BF16(acc[mt][nt], al[mt], bh[nt]);
                }
        }
        __syncthreads();
    }

    // ---- epilogue: bias + store
    const int mrow = lane >> 2;
    const int ncol = (lane & 3) * 2;
    #pragma unroll
    for (int mt = 0; mt < 4; mt++) {
        #pragma unroll
        for (int nt = 0; nt < 4; nt++) {
            int n = bn + wn * 32 + nt * 8 + ncol;
            float2 bv = *(const float2*)(bias + n);
            #pragma unroll
            for (int half = 0; half < 2; half++) {
                int m = bm + wm * 64 + mt * 16 + mrow + half * 8;
                float2 v;
                v.x = acc[mt][nt][half * 2 + 0] + bv.x;
                v.y = acc[mt][nt][half * 2 + 1] + bv.y;
                if (mode == 0) {
                    *(float2*)(C + (size_t)m * N + n) = v;
                } else {
                    int which = n >> 10;
                    int rem = n & 1023;
                    int h = rem >> 6;
                    int dcol = rem & 63;
                    int b = m >> 11;
                    int l = m & 2047;
                    float* dst = (which == 0) ? qo : (which == 1) ? ko : vo;
                    *(float2*)(dst +
                               ((((size_t)(b * Hq + h)) * Lq + l) * HDq + dcol)) = v;
                }
            }
        }
    }
}

// ---------------------------------------------------------------------------
// Flash attention (causal) — unchanged (fma-pipe fp32). Round-8 target.
// ---------------------------------------------------------------------------
#define ATTN_PAD 68
#define ATTN_SMEM_FLOATS (128 * ATTN_PAD + 128 * ATTN_PAD + \
                          64 * ATTN_PAD + 64 * ATTN_PAD + 3 * 128)
#define ATTN_SMEM_BYTES (ATTN_SMEM_FLOATS * 4)

__global__ __launch_bounds__(256, 2)
void attn_kernel(const float* __restrict__ q, const float* __restrict__ k,
                 const float* __restrict__ v, float* __restrict__ o) {
    extern __shared__ float sm[];
    float* Qs = sm;
    float* Ss = Qs + 128 * ATTN_PAD;
    float* Ks = Ss + 128 * ATTN_PAD;
    float* Vs = Ks + 64 * ATTN_PAD;
    float* mrow = Vs + 64 * ATTN_PAD;
    float* lrow = mrow + 128;
    float* arow = lrow + 128;

    const int bh = blockIdx.y;
    const int qt = (int)gridDim.x - 1 - blockIdx.x;
    const int tid = threadIdx.x;
    const int tx = tid & 15;
    const int ty = tid >> 4;
    const size_t base = (size_t)bh * Lq * HDq;
    const int q0 = qt * 128;

    for (int idx = tid; idx < 128 * 16; idx += 256) {
        int row = idx >> 4;
        int c4 = (idx & 15) << 2;
        float4 t = *(const float4*)(q + base + (size_t)(q0 + row) * HDq + c4);
        float* dst = &Qs[row * ATTN_PAD + c4];
        dst[0] = t.x * 0.125f;
        dst[1] = t.y * 0.125f;
        dst[2] = t.z * 0.125f;
        dst[3] = t.w * 0.125f;
    }
    if (tid < 128) {
        mrow[tid] = -1e30f;
        lrow[tid] = 0.0f;
    }

    float accO[8][4];
    #pragma unroll
    for (int i = 0; i < 8; i++)
        #pragma unroll
        for (int d = 0; d < 4; d++) accO[i][d] = 0.0f;

    const int nkt = 2 * qt + 2;
    for (int kt = 0; kt < nkt; kt++) {
        const int k0 = kt * 64;
        __syncthreads();

        for (int idx = tid; idx < 64 * 16; idx += 256) {
            int row = idx >> 4;
            int c4 = (idx & 15) << 2;
            *(float4*)&Ks[row * ATTN_PAD + c4] =
                *(const float4*)(k + base + (size_t)(k0 + row) * HDq + c4);
            *(float4*)&Vs[row * ATTN_PAD + c4] =
                *(const float4*)(v + base + (size_t)(k0 + row) * HDq + c4);
        }
        __syncthreads();

        float sacc[8][4];
        #pragma unroll
        for (int i = 0; i < 8; i++)
            #pragma unroll
            for (int j = 0; j < 4; j++) sacc[i][j] = 0.0f;

        #pragma unroll 2
        for (int d = 0; d < 64; d += 4) {
            float br[4][4];
            #pragma unroll
            for (int j = 0; j < 4; j++)
                *(float4*)br[j] = *(const float4*)&Ks[(tx * 4 + j) * ATTN_PAD + d];
            #pragma unroll
            for (int i = 0; i < 8; i++) {
                float ar[4];
                *(float4*)ar = *(const float4*)&Qs[(ty * 8 + i) * ATTN_PAD + d];
                #pragma unroll
                for (int j = 0; j < 4; j++)
                    #pragma unroll
                    for (int dd = 0; dd < 4; dd++)
                        sacc[i][j] += ar[dd] * br[j][dd];
            }
        }

        const bool masked_tile = (kt >= 2 * qt);
        #pragma unroll
        for (int i = 0; i < 8; i++) {
            int ig = q0 + ty * 8 + i;
            #pragma unroll
            for (int j = 0; j < 4; j++) {
                int jg = k0 + tx * 4 + j;
                float sv = sacc[i][j];
                if (masked_tile && jg > ig) sv = -1e30f;
                Ss[(ty * 8 + i) * ATTN_PAD + tx * 4 + j] = sv;
            }
        }
        __syncthreads();

        if (tid < 128) {
            float mold = mrow[tid];
            float mx = mold;
            float* srow = &Ss[tid * ATTN_PAD];
            #pragma unroll 8
            for (int j = 0; j < 64; j++) mx = fmaxf(mx, srow[j]);
            float al = __expf(mold - mx);
            float sum = 0.0f;
            #pragma unroll 8
            for (int j = 0; j < 64; j++) {
                float p = __expf(srow[j] - mx);
                srow[j] = p;
                sum += p;
            }
            lrow[tid] = lrow[tid] * al + sum;
            mrow[tid] = mx;
            arow[tid] = al;
        }
        __syncthreads();

        #pragma unroll
        for (int i = 0; i < 8; i++) {
            float al = arow[ty * 8 + i];
            #pragma unroll
            for (int dd = 0; dd < 4; dd++) accO[i][dd] *= al;
        }

        #pragma unroll 2
        for (int j = 0; j < 64; j += 4) {
            float vr[4][4];
            #pragma unroll
            for (int jj = 0; jj < 4; jj++)
                *(float4*)vr[jj] = *(const float4*)&Vs[(j + jj) * ATTN_PAD + tx * 4];
            #pragma unroll
            for (int i = 0; i < 8; i++) {
                float pr[4];
                *(float4*)pr = *(const float4*)&Ss[(ty * 8 + i) * ATTN_PAD + j];
                #pragma unroll
                for (int jj = 0; jj < 4; jj++)
                    #pragma unroll
                    for (int dd = 0; dd < 4; dd++)
                        accO[i][dd] += pr[jj] * vr[jj][dd];
            }
        }
    }

    const int b = bh >> 4;
    const int h = bh & 15;
    #pragma unroll
    for (int i = 0; i < 8; i++) {
        int row = q0 + ty * 8 + i;
        float linv = 1.0f / lrow[ty * 8 + i];
        float4 t;
        t.x = accO[i][0] * linv;
        t.y = accO[i][1] * linv;
        t.z = accO[i][2] * linv;
        t.w = accO[i][3] * linv;
        size_t dst = (((size_t)b * Lq + row) * Hq + h) * HDq + tx * 4;
        *(float4*)(o + dst) = t;
    }
}

// ---------------------------------------------------------------------------
// Launch
// ---------------------------------------------------------------------------
extern "C" void kernel_launch(void* const* d_in, const int* in_sizes, int n_in,
                              void* d_out, int out_size) {
    const float* x  = (const float*)d_in[0];
    const float* Wa = (const float*)d_in[1];
    const float* ba = (const float*)d_in[2];
    const float* Wp = (const float*)d_in[3];
    const float* bp = (const float*)d_in[4];
    float* out = (float*)d_out;

    float *gq, *gk, *gv, *go;
    cudaGetSymbolAddress((void**)&gq, g_q);
    cudaGetSymbolAddress((void**)&gk, g_k);
    cudaGetSymbolAddress((void**)&gv, g_v);
    cudaGetSymbolAddress((void**)&go, g_o);
    __nv_bfloat16 *ahi, *alo, *wahi, *walo, *wphi, *wplo;
    cudaGetSymbolAddress((void**)&ahi, g_ahi);
    cudaGetSymbolAddress((void**)&alo, g_alo);
    cudaGetSymbolAddress((void**)&wahi, g_wahi);
    cudaGetSymbolAddress((void**)&walo, g_walo);
    cudaGetSymbolAddress((void**)&wphi, g_wphi);
    cudaGetSymbolAddress((void**)&wplo, g_wplo);

    cudaFuncSetAttribute(mma_gemm, cudaFuncAttributeMaxDynamicSharedMemorySize,
                         GEMM_SMEM);
    cudaFuncSetAttribute(attn_kernel, cudaFuncAttributeMaxDynamicSharedMemorySize,
                         ATTN_SMEM_BYTES);

    // Split inputs to bf16 hi/lo
    split_kernel<<<8192, 256>>>(x, ahi, alo, 8192 * 1024);
    wsplit_kernel<<<dim3(96, 32), 256>>>(Wa, wahi, walo, 3072);
    wsplit_kernel<<<dim3(32, 32), 256>>>(Wp, wphi, wplo, 1024);

    // 1) QKV projection on tensor cores, scatter to q/k/v [B,H,L,Hd]
    mma_gemm<<<dim3(24, 64), 256, GEMM_SMEM>>>(ahi, alo, wahi, walo, ba, nullptr,
                                               3072, 1, gq, gk, gv);

    // 2) causal flash attention (fp32)
    attn_kernel<<<dim3(Lq / 128, Bq * Hq), 256, ATTN_SMEM_BYTES>>>(gq, gk, gv, go);

    // 3) output projection on tensor cores
    split_kernel<<<8192, 256>>>(go, ahi, alo, 8192 * 1024);
    mma_gemm<<<dim3(8, 64), 256, GEMM_SMEM>>>(ahi, alo, wphi, wplo, bp, out, 1024,
                                              0, nullptr, nullptr, nullptr);
}

// round 10
// speedup vs baseline: 2.8697x; 2.0945x over previous
#include <cuda_runtime.h>
#include <cuda_bf16.h>
#include <cstdint>
#include <cstddef>

// ---------------------------------------------------------------------------
// Problem: B=4, L=2048, D=1024, H=16, Hd=64
//   qkv = x @ W_attn + b_attn            [8192 x 3072]
//   attn (causal, 16 heads, softmax)      -> o [8192 x 1024]
//   out = o @ W_proj + b_proj             [8192 x 1024]
// Round 9: GEMMs 2-stage/2-CTA-per-SM; attention on mma.sync bf16 (hi/lo
// 3-pass for S and PV); o written as bf16 hi/lo directly.
// tcgen05 unusable: harness PTX targets sm_103 (no 'a' feature set).
// ---------------------------------------------------------------------------

#define Bq 4
#define Lq 2048
#define Hq 16
#define HDq 64

// bf16 split scratch
__device__ __nv_bfloat16 g_ahi[8192 * 1024];   // x / o (hi)
__device__ __nv_bfloat16 g_alo[8192 * 1024];   // x / o (lo)
__device__ __nv_bfloat16 g_wahi[3072 * 1024];  // W_attn^T split
__device__ __nv_bfloat16 g_walo[3072 * 1024];
__device__ __nv_bfloat16 g_wphi[1024 * 1024];  // W_proj^T split
__device__ __nv_bfloat16 g_wplo[1024 * 1024];
// qkv bf16 hi/lo; q pre-scaled by 0.125; v stored TRANSPOSED [b,h,d,l]
__device__ __nv_bfloat16 g_qhi[64 * 2048 * 64];
__device__ __nv_bfloat16 g_qlo[64 * 2048 * 64];
__device__ __nv_bfloat16 g_khi[64 * 2048 * 64];
__device__ __nv_bfloat16 g_klo[64 * 2048 * 64];
__device__ __nv_bfloat16 g_vhi[64 * 64 * 2048];
__device__ __nv_bfloat16 g_vlo[64 * 64 * 2048];

__device__ __forceinline__ uint32_t smem_to_u32(const void* p) {
    uint32_t a;
    asm("{ .reg .u64 t; cvta.to.shared.u64 t, %1; cvt.u32.u64 %0, t; }"
        : "=r"(a) : "l"(p));
    return a;
}

#define LDMATRIX_X4(r0, r1, r2, r3, addr) \
    asm volatile("ldmatrix.sync.aligned.m8n8.x4.shared.b16 {%0,%1,%2,%3}, [%4];" \
                 : "=r"(r0), "=r"(r1), "=r"(r2), "=r"(r3) : "r"(addr))

#define MMA_BF16(c, a, b) \
    asm volatile( \
        "mma.sync.aligned.m16n8k16.row.col.f32.bf16.bf16.f32 " \
        "{%0,%1,%2,%3}, {%4,%5,%6,%7}, {%8,%9}, {%0,%1,%2,%3};" \
        : "+f"((c)[0]), "+f"((c)[1]), "+f"((c)[2]), "+f"((c)[3]) \
        : "r"((a)[0]), "r"((a)[1]), "r"((a)[2]), "r"((a)[3]), \
          "r"((b)[0]), "r"((b)[1]))

#define CP_ASYNC16(dst, src) \
    asm volatile("cp.async.cg.shared.global [%0], [%1], 16;" \
                 :: "r"(dst), "l"(src))
#define CP_COMMIT() asm volatile("cp.async.commit_group;" ::: "memory")
#define CP_WAIT0() asm volatile("cp.async.wait_group 0;" ::: "memory")
#define CP_WAIT1() asm volatile("cp.async.wait_group 1;" ::: "memory")

// pack two floats -> bf16x2 (lo = first arg), plus residual split
__device__ __forceinline__ uint32_t cvt_bf162(float lo, float hi) {
    uint32_t r;
    asm("cvt.rn.bf16x2.f32 %0, %1, %2;" : "=r"(r) : "f"(hi), "f"(lo));
    return r;
}
__device__ __forceinline__ void split2(float x, float y, uint32_t& h, uint32_t& l) {
    h = cvt_bf162(x, y);
    float xr = x - __int_as_float(h << 16);
    float yr = y - __int_as_float(h & 0xFFFF0000u);
    l = cvt_bf162(xr, yr);
}

// ---------------------------------------------------------------------------
// Split kernels: fp32 -> bf16 hi + bf16 lo
// ---------------------------------------------------------------------------
__global__ void split_kernel(const float* __restrict__ in,
                             __nv_bfloat16* __restrict__ hi,
                             __nv_bfloat16* __restrict__ lo, int n) {
    int i = (blockIdx.x * blockDim.x + threadIdx.x) * 4;
    if (i >= n) return;
    float4 v = *(const float4*)(in + i);
    uint32_t h0, l0, h1, l1;
    split2(v.x, v.y, h0, l0);
    split2(v.z, v.w, h1, l1);
    *(uint32_t*)(hi + i) = h0;
    *(uint32_t*)(hi + i + 2) = h1;
    *(uint32_t*)(lo + i) = l0;
    *(uint32_t*)(lo + i + 2) = l1;
}

// W [1024, Ncols] -> Wt hi/lo [Ncols, 1024]  (transpose + split)
__global__ void wsplit_kernel(const float* __restrict__ W,
                              __nv_bfloat16* __restrict__ hi,
                              __nv_bfloat16* __restrict__ lo, int Ncols) {
    __shared__ float t[32][33];
    int n0 = blockIdx.x * 32, k0 = blockIdx.y * 32;
    int tx = threadIdx.x & 31, ty = threadIdx.x >> 5;  // 32 x 8
    #pragma unroll
    for (int r = 0; r < 32; r += 8)
        t[ty + r][tx] = W[(size_t)(k0 + ty + r) * Ncols + n0 + tx];
    __syncthreads();
    #pragma unroll
    for (int r = 0; r < 32; r += 8) {
        float v = t[tx][ty + r];  // W[k0+tx][n0+ty+r]
        __nv_bfloat16 h = __float2bfloat16(v);
        size_t di = (size_t)(n0 + ty + r) * 1024 + k0 + tx;
        hi[di] = h;
        lo[di] = __float2bfloat16(v - __bfloat162float(h));
    }
}

// ---------------------------------------------------------------------------
// mma.sync GEMM: C[M,N] = Asplit[M,1024] @ Bsplit[N,1024]^T + bias
// 128x128 CTA tile, 8 warps (2x4 -> 64x32 warp tile), Kc=32 chunks,
// 2-stage cp.async pipeline (2 CTAs/SM), hi/lo 3-pass accumulation.
// mode 0: row-major fp32 C store.
// mode 1: qkv epilogue -> bf16 hi/lo arrays (q scaled 0.125; v transposed).
// ---------------------------------------------------------------------------
#define KCH 32
#define NCHUNK 32
#define ROWP 40                        // padded row in bf16 (80B = 5x16B)
#define TILEB (128 * ROWP * 2)         // 10240 bytes per tile
#define STAGEB (4 * TILEB)             // Ahi, Alo, Bhi, Blo
#define GEMM_SMEM (2 * STAGEB)         // 81920

__global__ __launch_bounds__(256, 2)
void mma_gemm(const __nv_bfloat16* __restrict__ Ahi,
              const __nv_bfloat16* __restrict__ Alo,
              const __nv_bfloat16* __restrict__ Bhi,
              const __nv_bfloat16* __restrict__ Blo,
              const float* __restrict__ bias, float* __restrict__ C, int N,
              int mode,
              __nv_bfloat16* __restrict__ qh_, __nv_bfloat16* __restrict__ ql_,
              __nv_bfloat16* __restrict__ kh_, __nv_bfloat16* __restrict__ kl_,
              __nv_bfloat16* __restrict__ vh_, __nv_bfloat16* __restrict__ vl_) {
    extern __shared__ __align__(128) char smem[];
    const uint32_t smem_u32 = smem_to_u32(smem);
    const int tid = threadIdx.x;
    const int wid = tid >> 5;
    const int lane = tid & 31;
    const int wm = wid >> 2;
    const int wn = wid & 3;
    const int bn = blockIdx.x * 128;
    const int bm = blockIdx.y * 128;

    float acc[4][4][4];
    #pragma unroll
    for (int mt = 0; mt < 4; mt++)
        #pragma unroll
        for (int nt = 0; nt < 4; nt++)
            #pragma unroll
            for (int r = 0; r < 4; r++) acc[mt][nt][r] = 0.0f;

    auto load_stage = [&](int kc, int stage) {
        const int k0 = kc * KCH;
        const uint32_t sb = smem_u32 + stage * STAGEB;
        #pragma unroll
        for (int t = 0; t < 4; t++) {
            const __nv_bfloat16* src =
                (t == 0) ? Ahi : (t == 1) ? Alo : (t == 2) ? Bhi : Blo;
            const int rbase = (t < 2) ? bm : bn;
            #pragma unroll
            for (int s = 0; s < 2; s++) {
                int idx = s * 256 + tid;
                int row = idx >> 2;
                int c4 = idx & 3;
                const void* g = src + (size_t)(rbase + row) * 1024 + k0 + c4 * 8;
                uint32_t d = sb + t * TILEB + row * 80 + c4 * 16;
                CP_ASYNC16(d, g);
            }
        }
        CP_COMMIT();
    };

    load_stage(0, 0);
    load_stage(1, 1);

    const int amat = lane >> 3;
    const int rowin = lane & 7;
    const int am_base = wm * 64 + (amat & 1) * 8 + rowin;
    const int ak_base = (amat >> 1) * 8;
    const int bn_base = wn * 32 + ((lane >> 3) >> 1) * 8 + rowin;
    const int bk_base = ((lane >> 3) & 1) * 8;

    for (int kc = 0; kc < NCHUNK; kc++) {
        if (kc + 1 < NCHUNK) CP_WAIT1(); else CP_WAIT0();
        __syncthreads();

        const uint32_t sb = smem_u32 + (kc & 1) * STAGEB;
        #pragma unroll
        for (int ks = 0; ks < 2; ks++) {
            const int kb = ks * 16;
            uint32_t ah[4][4], al[4][4], bh[4][2], bl[4][2];
            #pragma unroll
            for (int mt = 0; mt < 4; mt++) {
                uint32_t a = sb + (am_base + mt * 16) * 80 + (ak_base + kb) * 2;
                LDMATRIX_X4(ah[mt][0], ah[mt][1], ah[mt][2], ah[mt][3], a);
                LDMATRIX_X4(al[mt][0], al[mt][1], al[mt][2], al[mt][3], a + TILEB);
            }
            #pragma unroll
            for (int np = 0; np < 2; np++) {
                uint32_t b = sb + 2 * TILEB + (bn_base + np * 16) * 80 +
                             (bk_base + kb) * 2;
                LDMATRIX_X4(bh[np * 2][0], bh[np * 2][1],
                            bh[np * 2 + 1][0], bh[np * 2 + 1][1], b);
                LDMATRIX_X4(bl[np * 2][0], bl[np * 2][1],
                            bl[np * 2 + 1][0], bl[np * 2 + 1][1], b + TILEB);
            }
            #pragma unroll
            for (int mt = 0; mt < 4; mt++)
                #pragma unroll
                for (int nt = 0; nt < 4; nt++) {
                    MMA_BF16(acc[mt][nt], ah[mt], bh[nt]);
                    MMA_BF16(acc[mt][nt], ah[mt], bl[nt]);
                    MMA_BF16(acc[mt][nt], al[mt], bh[nt]);
                }
        }
        __syncthreads();
        if (kc + 2 < NCHUNK) load_stage(kc + 2, kc & 1);
    }

    // ---- epilogue
    const int mrow = lane >> 2;
    const int ncol = (lane & 3) * 2;
    #pragma unroll
    for (int mt = 0; mt < 4; mt++) {
        #pragma unroll
        for (int nt = 0; nt < 4; nt++) {
            int n = bn + wn * 32 + nt * 8 + ncol;
            float2 bv = *(const float2*)(bias + n);
            #pragma unroll
            for (int half = 0; half < 2; half++) {
                int m = bm + wm * 64 + mt * 16 + mrow + half * 8;
                float2 v;
                v.x = acc[mt][nt][half * 2 + 0] + bv.x;
                v.y = acc[mt][nt][half * 2 + 1] + bv.y;
                if (mode == 0) {
                    *(float2*)(C + (size_t)m * N + n) = v;
                } else {
                    int which = n >> 10;
                    int rem = n & 1023;
                    int h = rem >> 6;
                    int d = rem & 63;
                    int b = m >> 11;
                    int l = m & 2047;
                    int bh = b * Hq + h;
                    if (which == 0) {
                        uint32_t h2, l2;
                        split2(v.x * 0.125f, v.y * 0.125f, h2, l2);
                        size_t di = ((size_t)bh * Lq + l) * HDq + d;
                        *(uint32_t*)(qh_ + di) = h2;
                        *(uint32_t*)(ql_ + di) = l2;
                    } else if (which == 1) {
                        uint32_t h2, l2;
                        split2(v.x, v.y, h2, l2);
                        size_t di = ((size_t)bh * Lq + l) * HDq + d;
                        *(uint32_t*)(kh_ + di) = h2;
                        *(uint32_t*)(kl_ + di) = l2;
                    } else {
                        // v transposed: [bh][d][l]
                        size_t base = ((size_t)bh * HDq + d) * Lq + l;
                        __nv_bfloat16 h0 = __float2bfloat16(v.x);
                        vh_[base] = h0;
                        vl_[base] = __float2bfloat16(v.x - __bfloat162float(h0));
                        __nv_bfloat16 h1 = __float2bfloat16(v.y);
                        vh_[base + Lq] = h1;
                        vl_[base + Lq] = __float2bfloat16(v.y - __bfloat162float(h1));
                    }
                }
            }
        }
    }
}

// ---------------------------------------------------------------------------
// Flash attention (causal) on mma.sync bf16, 3-pass hi/lo for S and PV.
// CTA: one (bh, 128-row q tile). 8 warps; warp w owns rows [w*16, w*16+16).
// Bc = 64 keys/iter, 2-stage cp.async on K/V (hi/lo); V pre-transposed.
// Writes o as bf16 hi/lo (feeds GEMM2 directly).
// Smem: Qhi 0, Qlo 18432; stage s at 36864 + s*36864:
//       Khi +0, Klo +9216, Vhi +18432, Vlo +27648 (rows padded to 144B).
// ---------------------------------------------------------------------------
#define AROWB 144
#define ATTN_SMEM 110592

__global__ __launch_bounds__(256, 2)
void attn_mma(const __nv_bfloat16* __restrict__ qhi,
              const __nv_bfloat16* __restrict__ qlo,
              const __nv_bfloat16* __restrict__ khi,
              const __nv_bfloat16* __restrict__ klo,
              const __nv_bfloat16* __restrict__ vhi,
              const __nv_bfloat16* __restrict__ vlo,
              __nv_bfloat16* __restrict__ ohi,
              __nv_bfloat16* __restrict__ olo) {
    extern __shared__ __align__(128) char smem[];
    const uint32_t su = smem_to_u32(smem);
    const int bh = blockIdx.y;
    const int qt = (int)gridDim.x - 1 - blockIdx.x;   // heavy tiles first
    const int q0 = qt * 128;
    const int tid = threadIdx.x;
    const int wid = tid >> 5;
    const int lane = tid & 31;
    const int r0 = wid * 16;
    const int rowin = lane & 7;
    const int g1 = (lane >> 3) & 1;   // A: m-part selector, B: k-part
    const int g2 = (lane >> 3) >> 1;  // A: k-part selector, B: n-part

    auto load_kv = [&](int kt2, int st) {
        const int k0 = kt2 * 64;
        const uint32_t sb = su + 36864 + st * 36864;
        #pragma unroll
        for (int s = 0; s < 2; s++) {
            int idx = s * 256 + tid;
            int row = idx >> 3;
            int c = idx & 7;
            const __nv_bfloat16* gk = khi + ((size_t)bh * Lq + k0 + row) * HDq + c * 8;
            CP_ASYNC16(sb + row * AROWB + c * 16, gk);
            const __nv_bfloat16* gk2 = klo + ((size_t)bh * Lq + k0 + row) * HDq + c * 8;
            CP_ASYNC16(sb + 9216 + row * AROWB + c * 16, gk2);
            const __nv_bfloat16* gv = vhi + ((size_t)bh * HDq + row) * Lq + k0 + c * 8;
            CP_ASYNC16(sb + 18432 + row * AROWB + c * 16, gv);
            const __nv_bfloat16* gv2 = vlo + ((size_t)bh * HDq + row) * Lq + k0 + c * 8;
            CP_ASYNC16(sb + 27648 + row * AROWB + c * 16, gv2);
        }
        CP_COMMIT();
    };

    // prologue: Q (both tiles) + KV stage 0 in one group; KV stage 1 next
    #pragma unroll
    for (int s = 0; s < 4; s++) {
        int idx = s * 256 + tid;
        int row = idx >> 3;
        int c = idx & 7;
        const __nv_bfloat16* gq = qhi + ((size_t)bh * Lq + q0 + row) * HDq + c * 8;
        CP_ASYNC16(su + row * AROWB + c * 16, gq);
        const __nv_bfloat16* gq2 = qlo + ((size_t)bh * Lq + q0 + row) * HDq + c * 8;
        CP_ASYNC16(su + 18432 + row * AROWB + c * 16, gq2);
    }
    load_kv(0, 0);
    load_kv(1, 1);

    float oacc[8][4];
    #pragma unroll
    for (int nt = 0; nt < 8; nt++)
        #pragma unroll
        for (int r = 0; r < 4; r++) oacc[nt][r] = 0.0f;
    float mA = -1e30f, mB = -1e30f, lA = 0.0f, lB = 0.0f;

    const int nkt = 2 * qt + 2;
    for (int kt = 0; kt < nkt; kt++) {
        if (kt + 1 < nkt) CP_WAIT1(); else CP_WAIT0();
        __syncthreads();
        const uint32_t sb = su + 36864 + (kt & 1) * 36864;
        const int k0 = kt * 64;

        // ---- S = Qhi@Khi^T + Qhi@Klo^T + Qlo@Khi^T  (rows r0..r0+15 x 64 keys)
        float sacc[8][4];
        #pragma unroll
        for (int nt = 0; nt < 8; nt++)
            #pragma unroll
            for (int r = 0; r < 4; r++) sacc[nt][r] = 0.0f;

        #pragma unroll
        for (int kk = 0; kk < 4; kk++) {
            uint32_t qhf[4], qlf[4];
            uint32_t qa = su + (r0 + g1 * 8 + rowin) * AROWB + (kk * 16 + g2 * 8) * 2;
            LDMATRIX_X4(qhf[0], qhf[1], qhf[2], qhf[3], qa);
            LDMATRIX_X4(qlf[0], qlf[1], qlf[2], qlf[3], qa + 18432);
            #pragma unroll
            for (int np = 0; np < 4; np++) {
                uint32_t kbh[2][2], kbl[2][2];
                uint32_t ka = sb + (np * 16 + g2 * 8 + rowin) * AROWB +
                              (kk * 16 + g1 * 8) * 2;
                LDMATRIX_X4(kbh[0][0], kbh[0][1], kbh[1][0], kbh[1][1], ka);
                LDMATRIX_X4(kbl[0][0], kbl[0][1], kbl[1][0], kbl[1][1], ka + 9216);
                MMA_BF16(sacc[np * 2], qhf, kbh[0]);
                MMA_BF16(sacc[np * 2], qhf, kbl[0]);
                MMA_BF16(sacc[np * 2], qlf, kbh[0]);
                MMA_BF16(sacc[np * 2 + 1], qhf, kbh[1]);
                MMA_BF16(sacc[np * 2 + 1], qhf, kbl[1]);
                MMA_BF16(sacc[np * 2 + 1], qlf, kbh[1]);
            }
        }

        // ---- causal mask (only diagonal 128x128 block: kt >= 2*qt)
        const int rA = q0 + r0 + (lane >> 2);
        if (kt >= 2 * qt) {
            #pragma unroll
            for (int nt = 0; nt < 8; nt++) {
                int c0 = k0 + nt * 8 + (lane & 3) * 2;
                if (c0 > rA) sacc[nt][0] = -1e30f;
                if (c0 + 1 > rA) sacc[nt][1] = -1e30f;
                if (c0 > rA + 8) sacc[nt][2] = -1e30f;
                if (c0 + 1 > rA + 8) sacc[nt][3] = -1e30f;
            }
        }

        // ---- online softmax (rows rA, rA+8 per lane; quad holds the 64 cols)
        float mxA = -1e30f, mxB = -1e30f;
        #pragma unroll
        for (int nt = 0; nt < 8; nt++) {
            mxA = fmaxf(mxA, fmaxf(sacc[nt][0], sacc[nt][1]));
            mxB = fmaxf(mxB, fmaxf(sacc[nt][2], sacc[nt][3]));
        }
        mxA = fmaxf(mxA, __shfl_xor_sync(0xffffffffu, mxA, 1));
        mxA = fmaxf(mxA, __shfl_xor_sync(0xffffffffu, mxA, 2));
        mxB = fmaxf(mxB, __shfl_xor_sync(0xffffffffu, mxB, 1));
        mxB = fmaxf(mxB, __shfl_xor_sync(0xffffffffu, mxB, 2));
        float mnA = fmaxf(mA, mxA);
        float mnB = fmaxf(mB, mxB);
        float aA = __expf(mA - mnA);
        float aB = __expf(mB - mnB);
        mA = mnA;
        mB = mnB;
        float lsA = 0.0f, lsB = 0.0f;
        #pragma unroll
        for (int nt = 0; nt < 8; nt++) {
            float p0 = __expf(sacc[nt][0] - mA);
            float p1 = __expf(sacc[nt][1] - mA);
            float p2 = __expf(sacc[nt][2] - mB);
            float p3 = __expf(sacc[nt][3] - mB);
            sacc[nt][0] = p0; sacc[nt][1] = p1;
            sacc[nt][2] = p2; sacc[nt][3] = p3;
            lsA += p0 + p1;
            lsB += p2 + p3;
        }
        lA = lA * aA + lsA;
        lB = lB * aB + lsB;
        #pragma unroll
        for (int nt = 0; nt < 8; nt++) {
            oacc[nt][0] *= aA; oacc[nt][1] *= aA;
            oacc[nt][2] *= aB; oacc[nt][3] *= aB;
        }

        // ---- PV: O += Ph@Vhi + Ph@Vlo + Pl@Vhi  (P from regs, V^T in smem)
        #pragma unroll
        for (int kk2 = 0; kk2 < 4; kk2++) {
            const int t0 = kk2 * 2, t1 = t0 + 1;
            uint32_t ph[4], pl[4];
            split2(sacc[t0][0], sacc[t0][1], ph[0], pl[0]);
            split2(sacc[t0][2], sacc[t0][3], ph[1], pl[1]);
            split2(sacc[t1][0], sacc[t1][1], ph[2], pl[2]);
            split2(sacc[t1][2], sacc[t1][3], ph[3], pl[3]);
            #pragma unroll
            for (int np = 0; np < 4; np++) {
                uint32_t vbh[2][2], vbl[2][2];
                uint32_t va = sb + 18432 + (np * 16 + g2 * 8 + rowin) * AROWB +
                              (kk2 * 16 + g1 * 8) * 2;
                LDMATRIX_X4(vbh[0][0], vbh[0][1], vbh[1][0], vbh[1][1], va);
                LDMATRIX_X4(vbl[0][0], vbl[0][1], vbl[1][0], vbl[1][1], va + 9216);
                MMA_BF16(oacc[np * 2], ph, vbh[0]);
                MMA_BF16(oacc[np * 2], ph, vbl[0]);
                MMA_BF16(oacc[np * 2], pl, vbh[0]);
                MMA_BF16(oacc[np * 2 + 1], ph, vbh[1]);
                MMA_BF16(oacc[np * 2 + 1], ph, vbl[1]);
                MMA_BF16(oacc[np * 2 + 1], pl, vbh[1]);
            }
        }

        __syncthreads();
        if (kt + 2 < nkt) load_kv(kt + 2, kt & 1);
    }

    // ---- finalize: row-sum reduce over quad, normalize, store bf16 hi/lo
    lA += __shfl_xor_sync(0xffffffffu, lA, 1);
    lA += __shfl_xor_sync(0xffffffffu, lA, 2);
    lB += __shfl_xor_sync(0xffffffffu, lB, 1);
    lB += __shfl_xor_sync(0xffffffffu, lB, 2);
    float iA = 1.0f / lA;
    float iB = 1.0f / lB;

    const int b = bh >> 4;
    const int hh = bh & 15;
    const int rgA = q0 + r0 + (lane >> 2);
    #pragma unroll
    for (int nt = 0; nt < 8; nt++) {
        int d = nt * 8 + (lane & 3) * 2;
        size_t ia = ((size_t)(b * Lq + rgA)) * 1024 + hh * 64 + d;
        size_t ib = ((size_t)(b * Lq + rgA + 8)) * 1024 + hh * 64 + d;
        uint32_t h2, l2;
        split2(oacc[nt][0] * iA, oacc[nt][1] * iA, h2, l2);
        *(uint32_t*)(ohi + ia) = h2;
        *(uint32_t*)(olo + ia) = l2;
        split2(oacc[nt][2] * iB, oacc[nt][3] * iB, h2, l2);
        *(uint32_t*)(ohi + ib) = h2;
        *(uint32_t*)(olo + ib) = l2;
    }
}

// ---------------------------------------------------------------------------
// Launch
// ---------------------------------------------------------------------------
extern "C" void kernel_launch(void* const* d_in, const int* in_sizes, int n_in,
                              void* d_out, int out_size) {
    const float* x  = (const float*)d_in[0];
    const float* Wa = (const float*)d_in[1];
    const float* ba = (const float*)d_in[2];
    const float* Wp = (const float*)d_in[3];
    const float* bp = (const float*)d_in[4];
    float* out = (float*)d_out;

    __nv_bfloat16 *ahi, *alo, *wahi, *walo, *wphi, *wplo;
    __nv_bfloat16 *qhi, *qlo, *khi, *klo, *vhi, *vlo;
    cudaGetSymbolAddress((void**)&ahi, g_ahi);
    cudaGetSymbolAddress((void**)&alo, g_alo);
    cudaGetSymbolAddress((void**)&wahi, g_wahi);
    cudaGetSymbolAddress((void**)&walo, g_walo);
    cudaGetSymbolAddress((void**)&wphi, g_wphi);
    cudaGetSymbolAddress((void**)&wplo, g_wplo);
    cudaGetSymbolAddress((void**)&qhi, g_qhi);
    cudaGetSymbolAddress((void**)&qlo, g_qlo);
    cudaGetSymbolAddress((void**)&khi, g_khi);
    cudaGetSymbolAddress((void**)&klo, g_klo);
    cudaGetSymbolAddress((void**)&vhi, g_vhi);
    cudaGetSymbolAddress((void**)&vlo, g_vlo);

    cudaFuncSetAttribute(mma_gemm, cudaFuncAttributeMaxDynamicSharedMemorySize,
                         GEMM_SMEM);
    cudaFuncSetAttribute(attn_mma, cudaFuncAttributeMaxDynamicSharedMemorySize,
                         ATTN_SMEM);

    // Split inputs to bf16 hi/lo
    split_kernel<<<8192, 256>>>(x, ahi, alo, 8192 * 1024);
    wsplit_kernel<<<dim3(96, 32), 256>>>(Wa, wahi, walo, 3072);
    wsplit_kernel<<<dim3(32, 32), 256>>>(Wp, wphi, wplo, 1024);

    // 1) QKV projection -> bf16 hi/lo q(scaled)/k/v(transposed)
    mma_gemm<<<dim3(24, 64), 256, GEMM_SMEM>>>(
        ahi, alo, wahi, walo, ba, nullptr, 3072, 1,
        qhi, qlo, khi, klo, vhi, vlo);

    // 2) causal flash attention (tensor cores) -> o hi/lo into ahi/alo
    attn_mma<<<dim3(16, 64), 256, ATTN_SMEM>>>(qhi, qlo, khi, klo, vhi, vlo,
                                               ahi, alo);

    // 3) output projection
    mma_gemm<<<dim3(8, 64), 256, GEMM_SMEM>>>(
        ahi, alo, wphi, wplo, bp, out, 1024, 0,
        nullptr, nullptr, nullptr, nullptr, nullptr, nullptr);
}